// round 3
// baseline (speedup 1.0000x reference)
#include <cuda_runtime.h>
#include <cstdint>

// Problem constants (fixed by reference setup_inputs)
#define NIMG 8          // batch
#define HW   512        // image H=W
#define BLK  32         // block size
#define NB   16         // blocks per dim
#define NP   256        // regions
#define KPSF 64         // psf size
#define QD   65         // folded kernel dim
#define QSZ  (QD*QD)    // 4225
#define OUTD 127        // per-region output dim
#define SN   1024       // sensor dim

// Folded kernel: Q[p][u+1][v+1] = sum_{dy,dx in {0,1}} psf[p][u+dy][v+dx] (valid taps only)
__device__ float g_Q[NP * QSZ];

__global__ void build_q_kernel(const float* __restrict__ psf) {
    int p = blockIdx.x;
    const float* w = psf + (size_t)p * KPSF * KPSF;
    for (int i = threadIdx.x; i < QSZ; i += blockDim.x) {
        int r = i / QD, c = i % QD;       // r = u+1, c = v+1
        float s = 0.0f;
        #pragma unroll
        for (int dy = 0; dy < 2; ++dy) {
            int a = r - 1 + dy;
            if (a < 0 || a >= KPSF) continue;
            #pragma unroll
            for (int dx = 0; dx < 2; ++dx) {
                int b = c - 1 + dx;
                if (b < 0 || b >= KPSF) continue;
                s += w[a * KPSF + b];
            }
        }
        g_Q[p * QSZ + i] = s;
    }
}

// One CTA per (region p, 32x32 output tile). 8 warps; each warp owns 4
// consecutive output rows; each lane owns one x column. Accumulates all 8
// batch images as f32x2 pairs via fma.rn.f32x2 (2x fp32 throughput).
__global__ __launch_bounds__(256) void conv_scatter_kernel(
    const float* __restrict__ imgs,
    const float* __restrict__ xc,
    const float* __restrict__ yc,
    float* __restrict__ out)
{
    extern __shared__ float smem[];
    float* sBlk = smem;                 // [32*32][8]  (n innermost, 32B slots)
    float* sQ   = smem + BLK * BLK * NIMG;  // [65*65]

    const int p  = blockIdx.y;
    const int bh = p & 15, bw = p >> 4;
    const int tid = threadIdx.x;

    // Stage the 32x32 block of every image (n innermost for vector LDS later)
    const float* ibase = imgs + (size_t)(bh * BLK) * HW + bw * BLK;
    for (int i = tid; i < BLK * BLK; i += 256) {
        int by = i >> 5, bx = i & 31;
        const float* g = ibase + by * HW + bx;
        #pragma unroll
        for (int n = 0; n < NIMG; ++n)
            sBlk[i * NIMG + n] = g[(size_t)n * HW * HW];
    }
    // Stage folded kernel
    const float* gq = g_Q + p * QSZ;
    for (int i = tid; i < QSZ; i += 256) sQ[i] = gq[i];
    __syncthreads();

    const int tile = blockIdx.x;
    const int y0 = (tile >> 2) * 32, x0 = (tile & 3) * 32;
    const int warp = tid >> 5, lane = tid & 31;
    const int yb = y0 + warp * 4;       // this thread's 4 rows: yb..yb+3 (yb even)
    const int x  = x0 + lane;

    // Exact per-warp by range: 2by >= yb-64 and 2by <= yb+3
    const int by_lo = max(0, yb / 2 - 32);
    const int by_hi = min(31, yb / 2 + 1);
    // CTA-uniform bx range over x in [x0, x0+31]
    const int bx_lo = max(0, x0 / 2 - 32);
    const int bx_hi = min(31, (x0 + 31) / 2);

    unsigned long long acc[4][4];       // [row k][image pair j] packed f32x2
    #pragma unroll
    for (int k = 0; k < 4; ++k)
        #pragma unroll
        for (int j = 0; j < 4; ++j) acc[k][j] = 0ULL;

    for (int by = by_lo; by <= by_hi; ++by) {
        const int qr0 = 2 * by + 64 - yb;     // Q row index for k=0 (= u0+1)
        const float* blkRow = sBlk + ((by << 5) * NIMG);
        for (int bx = bx_lo; bx <= bx_hi; ++bx) {
            const int qc = 2 * bx + 64 - x;   // Q col index (= v+1)
            const bool cok = ((unsigned)qc <= 64u);
            const ulonglong2* bp =
                (const ulonglong2*)(blkRow + bx * NIMG);
            const ulonglong2 b01 = bp[0];     // images {0,1},{2,3}
            const ulonglong2 b23 = bp[1];     // images {4,5},{6,7}
            const int qidx0 = qr0 * QD + qc;
            #pragma unroll
            for (int k = 0; k < 4; ++k) {
                const int qr = qr0 - k;
                const float q =
                    (cok && (unsigned)qr <= 64u) ? sQ[qidx0 - k * QD] : 0.0f;
                unsigned long long q2;
                asm("mov.b64 %0, {%1, %1};" : "=l"(q2) : "f"(q));
                asm("fma.rn.f32x2 %0, %1, %2, %0;"
                    : "+l"(acc[k][0]) : "l"(b01.x), "l"(q2));
                asm("fma.rn.f32x2 %0, %1, %2, %0;"
                    : "+l"(acc[k][1]) : "l"(b01.y), "l"(q2));
                asm("fma.rn.f32x2 %0, %1, %2, %0;"
                    : "+l"(acc[k][2]) : "l"(b23.x), "l"(q2));
                asm("fma.rn.f32x2 %0, %1, %2, %0;"
                    : "+l"(acc[k][3]) : "l"(b23.y), "l"(q2));
            }
        }
    }

    // Scatter-add this tile into the sensor (footprints always in-bounds)
    const int ic = 512 + __float2int_rn(xc[p] * 1e6f);
    const int jc = 512 + __float2int_rn(yc[p] * 1e6f);
    const int I0 = ic - 63, J0 = jc - 63;
    if (x < OUTD) {
        const int J = J0 + x;
        #pragma unroll
        for (int k = 0; k < 4; ++k) {
            const int y = yb + k;
            if (y >= OUTD) break;
            float* o = out + (size_t)(I0 + y) * SN + J;
            #pragma unroll
            for (int j = 0; j < 4; ++j) {
                const float lo = __uint_as_float((unsigned)(acc[k][j]));
                const float hi = __uint_as_float((unsigned)(acc[k][j] >> 32));
                atomicAdd(o + (size_t)(2 * j)     * (SN * SN), lo);
                atomicAdd(o + (size_t)(2 * j + 1) * (SN * SN), hi);
            }
        }
    }
}

extern "C" void kernel_launch(void* const* d_in, const int* in_sizes, int n_in,
                              void* d_out, int out_size) {
    const float* imgs = (const float*)d_in[0];
    const float* psf  = (const float*)d_in[1];
    const float* xc   = (const float*)d_in[4];
    const float* yc   = (const float*)d_in[5];
    float* out = (float*)d_out;

    // Zero the sensor (capturable memset node)
    cudaMemsetAsync(out, 0, (size_t)out_size * sizeof(float), 0);

    // Build folded 65x65 kernels from the 64x64 PSFs
    build_q_kernel<<<NP, 256>>>(psf);

    // Main conv + scatter
    const int smemBytes = (BLK * BLK * NIMG + QSZ) * (int)sizeof(float); // 49668
    cudaFuncSetAttribute(conv_scatter_kernel,
                         cudaFuncAttributeMaxDynamicSharedMemorySize, smemBytes);
    dim3 grid(16, NP);
    conv_scatter_kernel<<<grid, 256, smemBytes>>>(imgs, xc, yc, out);
}